// round 5
// baseline (speedup 1.0000x reference)
#include <cuda_runtime.h>
#include <stdint.h>

#define NUM_USERS 100000
#define N_NODES   150000
#define D         64
#define D4        16
#define E_EDGES   1200000

// ---------------- device scratch (allocation-free) ----------------
__device__ float g_x0[N_NODES * D];        // x1 = A~ emb
__device__ float g_x1[N_NODES * D];        // x2 = A~ x1
__device__ int   g_degi[2 * N_NODES];      // [0,N): deg_row  [N,2N): deg_col
__device__ float g_inv [2 * N_NODES];      // rsqrt(deg) or 0
__device__ int   g_offs[N_NODES];          // CSR start per dst node (disjoint ranges)
__device__ int   g_cursor[N_NODES];        // fill cursors
__device__ int2  g_csr[E_EDGES];           // packed {src_row, norm_bits}
__device__ int   g_total;                  // range allocator

// ---------------- setup kernels ----------------

__global__ void k_deg(const int* __restrict__ row, const int* __restrict__ col) {
    int e = blockIdx.x * blockDim.x + threadIdx.x;
    if (e < E_EDGES) {
        atomicAdd(&g_degi[row[e]], 1);
        atomicAdd(&g_degi[N_NODES + col[e]], 1);
    }
}

__global__ void k_inv() {
    int i = blockIdx.x * blockDim.x + threadIdx.x;
    if (i < 2 * N_NODES) {
        int d = g_degi[i];
        g_inv[i] = (d > 0) ? rsqrtf((float)d) : 0.0f;
    }
    if (i == 0) g_total = 0;
}

// Disjoint CSR range allocation: warp scan + block aggregation -> 1 atomic/block.
__global__ void k_alloc() {
    __shared__ int s_wtot[8];
    __shared__ int s_base;
    int n    = blockIdx.x * 256 + threadIdx.x;
    int lane = threadIdx.x & 31;
    int wid  = threadIdx.x >> 5;
    int d    = (n < N_NODES) ? g_degi[N_NODES + n] : 0;

    int x = d;                                   // warp inclusive scan
    #pragma unroll
    for (int o = 1; o < 32; o <<= 1) {
        int y = __shfl_up_sync(0xffffffffu, x, o);
        if (lane >= o) x += y;
    }
    if (lane == 31) s_wtot[wid] = x;
    __syncthreads();
    if (wid == 0) {
        int v = (lane < 8) ? s_wtot[lane] : 0;
        #pragma unroll
        for (int o = 1; o < 8; o <<= 1) {
            int y = __shfl_up_sync(0xffffffffu, v, o);
            if (lane >= o) v += y;
        }
        if (lane < 8) s_wtot[lane] = v;          // inclusive warp-total scan
        if (lane == 7) s_base = atomicAdd(&g_total, v);
    }
    __syncthreads();
    int base = s_base + (wid > 0 ? s_wtot[wid - 1] : 0);
    if (n < N_NODES) {
        int excl = base + x - d;
        g_offs[n]   = excl;
        g_cursor[n] = excl;
    }
}

__global__ void k_fill(const int* __restrict__ row, const int* __restrict__ col) {
    int e = blockIdx.x * blockDim.x + threadIdx.x;
    if (e < E_EDGES) {
        int r = row[e], c = col[e];
        int slot = atomicAdd(&g_cursor[c], 1);
        float w = g_inv[r] * g_inv[N_NODES + c];
        g_csr[slot] = make_int2(r, __float_as_int(w));
    }
}

// ---------------- propagation layer: warp-per-node pull ----------------
// 32 lanes own one dst node. half = lane>>4 processes edges j = half, half+2, ...
// lane q = lane&15 owns float4 #q of the 64-dim row. Partial accumulators
// combined with shfl_xor(16); half 0 writes.
// FINAL=0: dst[n] = acc
// FINAL=1: out[n] = (emb[n] + x1[n] + src[n] + acc) * 0.25   (src holds x2)
template<int FINAL>
__global__ void k_layer(const float4* __restrict__ src,
                        float4* __restrict__ dst,
                        const float4* __restrict__ emb,
                        const float4* __restrict__ xa,
                        float4* __restrict__ out) {
    int t = blockIdx.x * blockDim.x + threadIdx.x;
    int n = t >> 5;
    if (n >= N_NODES) return;
    int lane = threadIdx.x & 31;
    int half = lane >> 4;
    int q    = lane & 15;

    int beg = __ldg(&g_offs[n]);
    int d   = __ldg(&g_degi[N_NODES + n]);

    float4 acc = make_float4(0.f, 0.f, 0.f, 0.f);
    for (int j = half; j < d; j += 2) {
        int2  e = __ldg(&g_csr[beg + j]);           // broadcast within half
        float w = __int_as_float(e.y);
        float4 v = __ldg(&src[e.x * D4 + q]);
        acc.x = fmaf(w, v.x, acc.x);
        acc.y = fmaf(w, v.y, acc.y);
        acc.z = fmaf(w, v.z, acc.z);
        acc.w = fmaf(w, v.w, acc.w);
    }
    acc.x += __shfl_xor_sync(0xffffffffu, acc.x, 16);
    acc.y += __shfl_xor_sync(0xffffffffu, acc.y, 16);
    acc.z += __shfl_xor_sync(0xffffffffu, acc.z, 16);
    acc.w += __shfl_xor_sync(0xffffffffu, acc.w, 16);

    if (half == 0) {
        int oi = n * D4 + q;
        if (FINAL == 0) {
            dst[oi] = acc;
        } else {
            float4 a = __ldg(&emb[oi]);
            float4 b = __ldg(&xa[oi]);
            float4 c = __ldg(&src[oi]);
            const float s = 0.25f;
            out[oi] = make_float4((a.x + b.x + c.x + acc.x) * s,
                                  (a.y + b.y + c.y + acc.y) * s,
                                  (a.z + b.z + c.z + acc.z) * s,
                                  (a.w + b.w + c.w + acc.w) * s);
        }
    }
}

// ---------------- launch ----------------

extern "C" void kernel_launch(void* const* d_in, const int* in_sizes, int n_in,
                              void* d_out, int out_size) {
    const int*   edge = (const int*)d_in[0];   // [2, E]
    const float* emb  = (const float*)d_in[1]; // [N, 64]
    float*       out  = (float*)d_out;

    const int* row = edge;
    const int* col = edge + E_EDGES;

    float4* x0p; cudaGetSymbolAddress((void**)&x0p, g_x0);
    float4* x1p; cudaGetSymbolAddress((void**)&x1p, g_x1);
    int*   degp; cudaGetSymbolAddress((void**)&degp, g_degi);

    const int TB = 256;
    const int gE    = (E_EDGES + TB - 1) / TB;
    const int gMeta = (2 * N_NODES + TB - 1) / TB;
    const int gN    = (N_NODES + TB - 1) / TB;
    const int gLyr  = (N_NODES * 32 + TB - 1) / TB;

    // CSR build
    cudaMemsetAsync(degp, 0, 2 * N_NODES * sizeof(int));
    k_deg<<<gE, TB>>>(row, col);
    k_inv<<<gMeta, TB>>>();
    k_alloc<<<gN, TB>>>();
    k_fill<<<gE, TB>>>(row, col);

    // 3 propagation layers; out accumulation fused into final epilogue
    k_layer<0><<<gLyr, TB>>>((const float4*)emb, x0p, nullptr, nullptr, nullptr);
    k_layer<0><<<gLyr, TB>>>((const float4*)x0p, x1p, nullptr, nullptr, nullptr);
    k_layer<1><<<gLyr, TB>>>((const float4*)x1p, nullptr,
                             (const float4*)emb, (const float4*)x0p, (float4*)out);
}

// round 6
// speedup vs baseline: 1.6010x; 1.6010x over previous
#include <cuda_runtime.h>
#include <cuda_fp16.h>
#include <stdint.h>

#define NUM_USERS 100000
#define N_NODES   150000
#define D         64
#define D4        16          // float4 per row
#define DH2       16          // uint2 (=4 halfs) per fp16 row
#define E_EDGES   1200000

// ---------------- device scratch (allocation-free) ----------------
__device__ uint2 g_eh[N_NODES * DH2];      // emb converted to fp16
__device__ uint2 g_h0[N_NODES * DH2];      // x1 (fp16)
__device__ uint2 g_h1[N_NODES * DH2];      // x2 (fp16)
__device__ int   g_degi[2 * N_NODES];      // [0,N): deg_row  [N,2N): deg_col
__device__ float g_inv [2 * N_NODES];      // rsqrt(deg) or 0
__device__ int   g_offs[N_NODES];          // CSR start per dst node (disjoint ranges)
__device__ int   g_cursor[N_NODES];        // fill cursors
__device__ int2  g_csr[E_EDGES];           // packed {src_row, norm_bits}
__device__ int   g_total;                  // range allocator

// ---------------- setup kernels ----------------

__global__ void k_deg(const int* __restrict__ row, const int* __restrict__ col) {
    int e = blockIdx.x * blockDim.x + threadIdx.x;
    if (e < E_EDGES) {
        atomicAdd(&g_degi[row[e]], 1);
        atomicAdd(&g_degi[N_NODES + col[e]], 1);
    }
}

__global__ void k_inv() {
    int i = blockIdx.x * blockDim.x + threadIdx.x;
    if (i < 2 * N_NODES) {
        int d = g_degi[i];
        g_inv[i] = (d > 0) ? rsqrtf((float)d) : 0.0f;
    }
    if (i == 0) g_total = 0;
}

// Disjoint CSR range allocation: warp scan + block aggregation -> 1 atomic/block.
__global__ void k_alloc() {
    __shared__ int s_wtot[8];
    __shared__ int s_base;
    int n    = blockIdx.x * 256 + threadIdx.x;
    int lane = threadIdx.x & 31;
    int wid  = threadIdx.x >> 5;
    int d    = (n < N_NODES) ? g_degi[N_NODES + n] : 0;

    int x = d;
    #pragma unroll
    for (int o = 1; o < 32; o <<= 1) {
        int y = __shfl_up_sync(0xffffffffu, x, o);
        if (lane >= o) x += y;
    }
    if (lane == 31) s_wtot[wid] = x;
    __syncthreads();
    if (wid == 0) {
        int v = (lane < 8) ? s_wtot[lane] : 0;
        #pragma unroll
        for (int o = 1; o < 8; o <<= 1) {
            int y = __shfl_up_sync(0xffffffffu, v, o);
            if (lane >= o) v += y;
        }
        if (lane < 8) s_wtot[lane] = v;
        if (lane == 7) s_base = atomicAdd(&g_total, v);
    }
    __syncthreads();
    int base = s_base + (wid > 0 ? s_wtot[wid - 1] : 0);
    if (n < N_NODES) {
        int excl = base + x - d;
        g_offs[n]   = excl;
        g_cursor[n] = excl;
    }
}

__global__ void k_fill(const int* __restrict__ row, const int* __restrict__ col) {
    int e = blockIdx.x * blockDim.x + threadIdx.x;
    if (e < E_EDGES) {
        int r = row[e], c = col[e];
        int slot = atomicAdd(&g_cursor[c], 1);
        float w = g_inv[r] * g_inv[N_NODES + c];
        g_csr[slot] = make_int2(r, __float_as_int(w));
    }
}

// emb fp32 -> fp16 copy (one float4 -> one uint2 per thread)
__global__ void k_cvt(const float4* __restrict__ src, uint2* __restrict__ dst) {
    int i = blockIdx.x * blockDim.x + threadIdx.x;
    if (i < N_NODES * D4) {
        float4 v = __ldg(&src[i]);
        __half2 h0 = __float22half2_rn(make_float2(v.x, v.y));
        __half2 h1 = __float22half2_rn(make_float2(v.z, v.w));
        uint2 o;
        o.x = *reinterpret_cast<unsigned*>(&h0);
        o.y = *reinterpret_cast<unsigned*>(&h1);
        dst[i] = o;
    }
}

// ---------------- propagation layer: 16-lane-per-node pull, fp16 storage ----
// Lane q owns halfs [4q, 4q+4) of the 64-dim row (one uint2 = 8B; the 16-lane
// gather is a single 128B cache line). Accumulate fp32 in registers.
// FINAL=0: dst[n] = half(acc)
// FINAL=1: out[n] = (emb_fp32[n] + x0h[n] + src[n] + acc) * 0.25   (src = x1h)
template<int FINAL>
__global__ void k_layerh(const uint2* __restrict__ src,
                         uint2* __restrict__ dst,
                         const float4* __restrict__ emb,
                         const uint2* __restrict__ xa,
                         float4* __restrict__ out) {
    int t = blockIdx.x * blockDim.x + threadIdx.x;
    int n = t >> 4;
    int q = t & 15;
    if (n >= N_NODES) return;

    int beg = __ldg(&g_offs[n]);
    int d   = __ldg(&g_degi[N_NODES + n]);

    float2 a0 = make_float2(0.f, 0.f);
    float2 a1 = make_float2(0.f, 0.f);

    int2 e;
    if (d > 0) e = __ldg(&g_csr[beg]);            // software prefetch pipeline
    for (int j = 0; j < d; ++j) {
        int   r = e.x;
        float w = __int_as_float(e.y);
        if (j + 1 < d) e = __ldg(&g_csr[beg + j + 1]);
        uint2 v = __ldg(&src[r * DH2 + q]);
        float2 f0 = __half22float2(*reinterpret_cast<__half2*>(&v.x));
        float2 f1 = __half22float2(*reinterpret_cast<__half2*>(&v.y));
        a0.x = fmaf(w, f0.x, a0.x);
        a0.y = fmaf(w, f0.y, a0.y);
        a1.x = fmaf(w, f1.x, a1.x);
        a1.y = fmaf(w, f1.y, a1.y);
    }

    int oi = n * DH2 + q;
    if (FINAL == 0) {
        __half2 h0 = __float22half2_rn(a0);
        __half2 h1 = __float22half2_rn(a1);
        uint2 o;
        o.x = *reinterpret_cast<unsigned*>(&h0);
        o.y = *reinterpret_cast<unsigned*>(&h1);
        dst[oi] = o;
    } else {
        float4 em = __ldg(&emb[oi]);
        uint2 va = __ldg(&xa[oi]);    // x0h
        uint2 vb = __ldg(&src[oi]);   // x1h
        float2 fa0 = __half22float2(*reinterpret_cast<__half2*>(&va.x));
        float2 fa1 = __half22float2(*reinterpret_cast<__half2*>(&va.y));
        float2 fb0 = __half22float2(*reinterpret_cast<__half2*>(&vb.x));
        float2 fb1 = __half22float2(*reinterpret_cast<__half2*>(&vb.y));
        const float s = 0.25f;
        out[oi] = make_float4((em.x + fa0.x + fb0.x + a0.x) * s,
                              (em.y + fa0.y + fb0.y + a0.y) * s,
                              (em.z + fa1.x + fb1.x + a1.x) * s,
                              (em.w + fa1.y + fb1.y + a1.y) * s);
    }
}

// ---------------- launch ----------------

extern "C" void kernel_launch(void* const* d_in, const int* in_sizes, int n_in,
                              void* d_out, int out_size) {
    const int*   edge = (const int*)d_in[0];   // [2, E]
    const float* emb  = (const float*)d_in[1]; // [N, 64]
    float*       out  = (float*)d_out;

    const int* row = edge;
    const int* col = edge + E_EDGES;

    uint2* ehp; cudaGetSymbolAddress((void**)&ehp, g_eh);
    uint2* h0p; cudaGetSymbolAddress((void**)&h0p, g_h0);
    uint2* h1p; cudaGetSymbolAddress((void**)&h1p, g_h1);
    int*  degp; cudaGetSymbolAddress((void**)&degp, g_degi);

    const int TB = 256;
    const int gE    = (E_EDGES + TB - 1) / TB;
    const int gMeta = (2 * N_NODES + TB - 1) / TB;
    const int gN    = (N_NODES + TB - 1) / TB;
    const int gCvt  = (N_NODES * D4 + TB - 1) / TB;
    const int gLyr  = (N_NODES * 16 + TB - 1) / TB;

    // CSR build + fp16 conversion of emb
    cudaMemsetAsync(degp, 0, 2 * N_NODES * sizeof(int));
    k_cvt<<<gCvt, TB>>>((const float4*)emb, ehp);
    k_deg<<<gE, TB>>>(row, col);
    k_inv<<<gMeta, TB>>>();
    k_alloc<<<gN, TB>>>();
    k_fill<<<gE, TB>>>(row, col);

    // 3 propagation layers; out accumulation fused into final epilogue
    k_layerh<0><<<gLyr, TB>>>(ehp, h0p, nullptr, nullptr, nullptr);
    k_layerh<0><<<gLyr, TB>>>(h0p, h1p, nullptr, nullptr, nullptr);
    k_layerh<1><<<gLyr, TB>>>(h1p, nullptr, (const float4*)emb, h0p, (float4*)out);
}